// round 12
// baseline (speedup 1.0000x reference)
#include <cuda_runtime.h>
#include <cuda_fp16.h>
#include <cuda_bf16.h>
#include <cstdint>

// Problem constants (fixed by the reference)
#define N_NODES 100000
#define N_PAD   100032      // padded to a multiple of 64 (GEMM tile)
#define N_EDGES 1600000
#define D       64
#define CAP     64          // ELL row capacity; Poisson(16) => P(deg>64) ~ 1e-20
#define TILE    64          // GEMM node tile

#define GEMM_BLOCKS (N_PAD / TILE)                 // 1563
#define FILL_BLOCKS ((N_EDGES / 8 + 255) / 256)    // 782

// ---------------------------------------------------------------------------
// Scratch (allocation-free rule: __device__ globals). Zero-initialized at
// module load. g_deg is left zeroed by the gather kernel after each launch.
// Row N_NODES of g_yh is never written and stays 0 (dummy row).
// ---------------------------------------------------------------------------
__device__ int    g_deg[N_NODES];
__device__ int    g_adj[(size_t)N_NODES * CAP];       // 25.6 MB, ELL layout
__device__ __half g_yh[(size_t)(N_NODES + 1) * D];    // 12.8 MB, y = x @ W (fp16)

// ---------------------------------------------------------------------------
// Kernel 1 (fused): blocks [0, GEMM_BLOCKS) compute y = x @ W (fp32 -> fp16);
// blocks [GEMM_BLOCKS, +FILL_BLOCKS) do the ELL fill (GEMM-first ordering:
// measured faster than fill-first in R11).
// ---------------------------------------------------------------------------
__global__ void transform_fill_kernel(const float* __restrict__ x,
                                      const float* __restrict__ W,
                                      const int*   __restrict__ ei) {
    int t = threadIdx.x;   // 0..255

    if (blockIdx.x >= GEMM_BLOCKS) {
        // ---------------- ELL fill: 8 edges per thread ----------------
        int i = (blockIdx.x - GEMM_BLOCKS) * 256 + t;
        int e = i * 8;
        if (e >= N_EDGES) return;   // N_EDGES % 8 == 0

        int4 sa = *reinterpret_cast<const int4*>(&ei[e]);
        int4 sb = *reinterpret_cast<const int4*>(&ei[e + 4]);
        int4 ta = *reinterpret_cast<const int4*>(&ei[N_EDGES + e]);
        int4 tb = *reinterpret_cast<const int4*>(&ei[N_EDGES + e + 4]);

        int s[8]  = { sa.x, sa.y, sa.z, sa.w, sb.x, sb.y, sb.z, sb.w };
        int tt[8] = { ta.x, ta.y, ta.z, ta.w, tb.x, tb.y, tb.z, tb.w };

        int p[8];
#pragma unroll
        for (int u = 0; u < 8; u++) p[u] = atomicAdd(&g_deg[s[u]], 1);
#pragma unroll
        for (int u = 0; u < 8; u++)
            if (p[u] < CAP) g_adj[(long)s[u] * CAP + p[u]] = tt[u];
        return;
    }

    // ---------------- tiled GEMM: y = x @ W ----------------
    __shared__ float As[TILE][68];
    __shared__ float Ws[D][68];

    int tile0 = blockIdx.x * TILE;

    {
        const float4* W4 = reinterpret_cast<const float4*>(W);
        for (int f = t; f < D * (D / 4); f += 256) {
            int k = f >> 4, jg = f & 15;
            *reinterpret_cast<float4*>(&Ws[k][jg * 4]) = W4[f];
        }
    }
    {
        for (int f = t; f < TILE * (D / 4); f += 256) {
            int node = f >> 4, kg = f & 15;
            int gn = tile0 + node;
            float4 v = make_float4(0.f, 0.f, 0.f, 0.f);
            if (gn < N_NODES)
                v = reinterpret_cast<const float4*>(x)[(size_t)gn * (D / 4) + kg];
            *reinterpret_cast<float4*>(&As[node][kg * 4]) = v;
        }
    }
    __syncthreads();

    int tx = t & 15;    // col group (4 cols)
    int ty = t >> 4;    // node group (4 rows)

    float acc[4][4];
#pragma unroll
    for (int r = 0; r < 4; r++)
#pragma unroll
        for (int c = 0; c < 4; c++) acc[r][c] = 0.f;

#pragma unroll 8
    for (int k = 0; k < D; k++) {
        float4 w = *reinterpret_cast<const float4*>(&Ws[k][tx * 4]);
        float a0 = As[ty * 4 + 0][k];
        float a1 = As[ty * 4 + 1][k];
        float a2 = As[ty * 4 + 2][k];
        float a3 = As[ty * 4 + 3][k];
        acc[0][0] += a0 * w.x; acc[0][1] += a0 * w.y; acc[0][2] += a0 * w.z; acc[0][3] += a0 * w.w;
        acc[1][0] += a1 * w.x; acc[1][1] += a1 * w.y; acc[1][2] += a1 * w.z; acc[1][3] += a1 * w.w;
        acc[2][0] += a2 * w.x; acc[2][1] += a2 * w.y; acc[2][2] += a2 * w.z; acc[2][3] += a2 * w.w;
        acc[3][0] += a3 * w.x; acc[3][1] += a3 * w.y; acc[3][2] += a3 * w.z; acc[3][3] += a3 * w.w;
    }

#pragma unroll
    for (int r = 0; r < 4; r++) {
        int node = tile0 + ty * 4 + r;
        if (node < N_NODES) {
            __half2 h0 = __floats2half2_rn(acc[r][0], acc[r][1]);
            __half2 h1 = __floats2half2_rn(acc[r][2], acc[r][3]);
            uint2 pk = make_uint2(*reinterpret_cast<unsigned int*>(&h0),
                                  *reinterpret_cast<unsigned int*>(&h1));
            *reinterpret_cast<uint2*>(&g_yh[(size_t)node * D + tx * 4]) = pk;
        }
    }
}

// ---------------------------------------------------------------------------
// Kernel 2: gather over y + normalize + bias -> out (final)
// One warp per node. Lane = (slot, colgrp): slot=lane>>3, cg=lane&7.
// Hot path: 4-neighbor batches summed as an fp16 quad-tree (12 HADD2) with
// ONE fp32 convert+add per half2 (vs per-row in R9): ~24 fma-pipe ops per
// batch instead of 48. All scalars named (no by-value struct helpers, no
// indexed arrays) to prevent local-memory demotion (R10 lesson).
// 32-bit offset math for y-row addressing.
// ---------------------------------------------------------------------------
__device__ __forceinline__ __half2 as_h2(unsigned int u) {
    union { unsigned int u; __half2 h; } c;
    c.u = u;
    return c.h;
}

__global__ void gather_kernel(const float* __restrict__ b,
                              float*       __restrict__ out) {
    int node = (blockIdx.x * blockDim.x + threadIdx.x) >> 5;
    int lane = threadIdx.x & 31;
    if (node >= N_NODES) return;

    int slot = lane >> 3;
    int cg   = lane & 7;

    const int* arow = &g_adj[(long)node * CAP];
    // independent loads: deg, adj row (unpredicated — always in bounds)
    int deg_raw = g_deg[node];
    int a0 = arow[lane];

    // reset for the next launch (replaces the zeroing kernel)
    if (lane == 0) g_deg[node] = 0;

    int deg = deg_raw > CAP ? CAP : deg_raw;
    int d0  = deg < 32 ? deg : 32;

    const uint4* y4 = reinterpret_cast<const uint4*>(g_yh);
    unsigned ucg = (unsigned)cg;

    float acc0 = 0.f, acc1 = 0.f, acc2 = 0.f, acc3 = 0.f;
    float acc4 = 0.f, acc5 = 0.f, acc6 = 0.f, acc7 = 0.f;

    // ---- neighbors 0..15: unconditional batch ----
    {
        int j0 = slot, j1 = slot + 4, j2 = slot + 8, j3 = slot + 12;
        int i0 = __shfl_sync(0xFFFFFFFFu, a0, j0);
        int i1 = __shfl_sync(0xFFFFFFFFu, a0, j1);
        int i2 = __shfl_sync(0xFFFFFFFFu, a0, j2);
        int i3 = __shfl_sync(0xFFFFFFFFu, a0, j3);
        unsigned o0 = (unsigned)((j0 < d0) ? i0 : N_NODES) * 8u + ucg;
        unsigned o1 = (unsigned)((j1 < d0) ? i1 : N_NODES) * 8u + ucg;
        unsigned o2 = (unsigned)((j2 < d0) ? i2 : N_NODES) * 8u + ucg;
        unsigned o3 = (unsigned)((j3 < d0) ? i3 : N_NODES) * 8u + ucg;
        uint4 v0 = y4[o0];
        uint4 v1 = y4[o1];
        uint4 v2 = y4[o2];
        uint4 v3 = y4[o3];
        __half2 s0 = __hadd2(as_h2(v0.x), as_h2(v1.x));
        __half2 s1 = __hadd2(as_h2(v0.y), as_h2(v1.y));
        __half2 s2 = __hadd2(as_h2(v0.z), as_h2(v1.z));
        __half2 s3 = __hadd2(as_h2(v0.w), as_h2(v1.w));
        __half2 r0 = __hadd2(as_h2(v2.x), as_h2(v3.x));
        __half2 r1 = __hadd2(as_h2(v2.y), as_h2(v3.y));
        __half2 r2 = __hadd2(as_h2(v2.z), as_h2(v3.z));
        __half2 r3 = __hadd2(as_h2(v2.w), as_h2(v3.w));
        float2 f0 = __half22float2(__hadd2(s0, r0));
        float2 f1 = __half22float2(__hadd2(s1, r1));
        float2 f2 = __half22float2(__hadd2(s2, r2));
        float2 f3 = __half22float2(__hadd2(s3, r3));
        acc0 += f0.x; acc1 += f0.y;
        acc2 += f1.x; acc3 += f1.y;
        acc4 += f2.x; acc5 += f2.y;
        acc6 += f3.x; acc7 += f3.y;
    }
    // ---- neighbors 16..31: warp-uniform branch (P ~ 0.43) ----
    if (d0 > 16) {
        int j0 = slot + 16, j1 = slot + 20, j2 = slot + 24, j3 = slot + 28;
        int i0 = __shfl_sync(0xFFFFFFFFu, a0, j0);
        int i1 = __shfl_sync(0xFFFFFFFFu, a0, j1);
        int i2 = __shfl_sync(0xFFFFFFFFu, a0, j2);
        int i3 = __shfl_sync(0xFFFFFFFFu, a0, j3);
        unsigned o0 = (unsigned)((j0 < d0) ? i0 : N_NODES) * 8u + ucg;
        unsigned o1 = (unsigned)((j1 < d0) ? i1 : N_NODES) * 8u + ucg;
        unsigned o2 = (unsigned)((j2 < d0) ? i2 : N_NODES) * 8u + ucg;
        unsigned o3 = (unsigned)((j3 < d0) ? i3 : N_NODES) * 8u + ucg;
        uint4 v0 = y4[o0];
        uint4 v1 = y4[o1];
        uint4 v2 = y4[o2];
        uint4 v3 = y4[o3];
        __half2 s0 = __hadd2(as_h2(v0.x), as_h2(v1.x));
        __half2 s1 = __hadd2(as_h2(v0.y), as_h2(v1.y));
        __half2 s2 = __hadd2(as_h2(v0.z), as_h2(v1.z));
        __half2 s3 = __hadd2(as_h2(v0.w), as_h2(v1.w));
        __half2 r0 = __hadd2(as_h2(v2.x), as_h2(v3.x));
        __half2 r1 = __hadd2(as_h2(v2.y), as_h2(v3.y));
        __half2 r2 = __hadd2(as_h2(v2.z), as_h2(v3.z));
        __half2 r3 = __hadd2(as_h2(v2.w), as_h2(v3.w));
        float2 f0 = __half22float2(__hadd2(s0, r0));
        float2 f1 = __half22float2(__hadd2(s1, r1));
        float2 f2 = __half22float2(__hadd2(s2, r2));
        float2 f3 = __half22float2(__hadd2(s3, r3));
        acc0 += f0.x; acc1 += f0.y;
        acc2 += f1.x; acc3 += f1.y;
        acc4 += f2.x; acc5 += f2.y;
        acc6 += f3.x; acc7 += f3.y;
    }
    // ---- neighbors 32..63: rare tail (P(deg>32) ~ 1e-4), two batches ----
    if (deg > 32) {
        int a1 = arow[32 + lane];
#pragma unroll
        for (int half = 0; half < 2; half++) {
            int base = 32 + half * 16;
            int j0 = base + slot, j1 = base + slot + 4;
            int j2 = base + slot + 8, j3 = base + slot + 12;
            int i0 = __shfl_sync(0xFFFFFFFFu, a1, j0 - 32);
            int i1 = __shfl_sync(0xFFFFFFFFu, a1, j1 - 32);
            int i2 = __shfl_sync(0xFFFFFFFFu, a1, j2 - 32);
            int i3 = __shfl_sync(0xFFFFFFFFu, a1, j3 - 32);
            unsigned o0 = (unsigned)((j0 < deg) ? i0 : N_NODES) * 8u + ucg;
            unsigned o1 = (unsigned)((j1 < deg) ? i1 : N_NODES) * 8u + ucg;
            unsigned o2 = (unsigned)((j2 < deg) ? i2 : N_NODES) * 8u + ucg;
            unsigned o3 = (unsigned)((j3 < deg) ? i3 : N_NODES) * 8u + ucg;
            uint4 v0 = y4[o0];
            uint4 v1 = y4[o1];
            uint4 v2 = y4[o2];
            uint4 v3 = y4[o3];
            __half2 s0 = __hadd2(as_h2(v0.x), as_h2(v1.x));
            __half2 s1 = __hadd2(as_h2(v0.y), as_h2(v1.y));
            __half2 s2 = __hadd2(as_h2(v0.z), as_h2(v1.z));
            __half2 s3 = __hadd2(as_h2(v0.w), as_h2(v1.w));
            __half2 r0 = __hadd2(as_h2(v2.x), as_h2(v3.x));
            __half2 r1 = __hadd2(as_h2(v2.y), as_h2(v3.y));
            __half2 r2 = __hadd2(as_h2(v2.z), as_h2(v3.z));
            __half2 r3 = __hadd2(as_h2(v2.w), as_h2(v3.w));
            float2 f0 = __half22float2(__hadd2(s0, r0));
            float2 f1 = __half22float2(__hadd2(s1, r1));
            float2 f2 = __half22float2(__hadd2(s2, r2));
            float2 f3 = __half22float2(__hadd2(s3, r3));
            acc0 += f0.x; acc1 += f0.y;
            acc2 += f1.x; acc3 += f1.y;
            acc4 += f2.x; acc5 += f2.y;
            acc6 += f3.x; acc7 += f3.y;
        }
    }

    // reduce across the 4 slots
    acc0 += __shfl_xor_sync(0xFFFFFFFFu, acc0, 8);
    acc1 += __shfl_xor_sync(0xFFFFFFFFu, acc1, 8);
    acc2 += __shfl_xor_sync(0xFFFFFFFFu, acc2, 8);
    acc3 += __shfl_xor_sync(0xFFFFFFFFu, acc3, 8);
    acc4 += __shfl_xor_sync(0xFFFFFFFFu, acc4, 8);
    acc5 += __shfl_xor_sync(0xFFFFFFFFu, acc5, 8);
    acc6 += __shfl_xor_sync(0xFFFFFFFFu, acc6, 8);
    acc7 += __shfl_xor_sync(0xFFFFFFFFu, acc7, 8);
    acc0 += __shfl_xor_sync(0xFFFFFFFFu, acc0, 16);
    acc1 += __shfl_xor_sync(0xFFFFFFFFu, acc1, 16);
    acc2 += __shfl_xor_sync(0xFFFFFFFFu, acc2, 16);
    acc3 += __shfl_xor_sync(0xFFFFFFFFu, acc3, 16);
    acc4 += __shfl_xor_sync(0xFFFFFFFFu, acc4, 16);
    acc5 += __shfl_xor_sync(0xFFFFFFFFu, acc5, 16);
    acc6 += __shfl_xor_sync(0xFFFFFFFFu, acc6, 16);
    acc7 += __shfl_xor_sync(0xFFFFFFFFu, acc7, 16);

    if (slot == 0) {
        float scale = 1.0f / ((float)deg_raw + 1e-6f);
        float4 b0 = reinterpret_cast<const float4*>(b)[cg * 2];
        float4 b1 = reinterpret_cast<const float4*>(b)[cg * 2 + 1];
        float4 o0 = make_float4(acc0 * scale + b0.x, acc1 * scale + b0.y,
                                acc2 * scale + b0.z, acc3 * scale + b0.w);
        float4 o1 = make_float4(acc4 * scale + b1.x, acc5 * scale + b1.y,
                                acc6 * scale + b1.z, acc7 * scale + b1.w);
        float4* dst = reinterpret_cast<float4*>(&out[(size_t)node * D + cg * 8]);
        dst[0] = o0;
        dst[1] = o1;
    }
}

// ---------------------------------------------------------------------------
// Launch
// ---------------------------------------------------------------------------
extern "C" void kernel_launch(void* const* d_in, const int* in_sizes, int n_in,
                              void* d_out, int out_size) {
    const float* x  = (const float*)d_in[0];   // [N, 64]
    const int*   ei = (const int*)  d_in[1];   // [2, E]
    const float* W  = (const float*)d_in[2];   // [64, 64]
    const float* b  = (const float*)d_in[3];   // [64]
    float* out = (float*)d_out;                // [N, 64]

    (void)in_sizes; (void)n_in; (void)out_size;

    transform_fill_kernel<<<GEMM_BLOCKS + FILL_BLOCKS, 256>>>(x, W, ei);

    // one warp per node, 8 warps per block
    gather_kernel<<<(N_NODES + 7) / 8, 256>>>(b, out);
}

// round 13
// speedup vs baseline: 2.0170x; 2.0170x over previous
#include <cuda_runtime.h>
#include <cuda_fp16.h>
#include <cuda_bf16.h>
#include <mma.h>
#include <cstdint>

// Problem constants (fixed by the reference)
#define N_NODES 100000
#define N_PAD   100096      // multiple of 128 (wmma GEMM block tile)
#define N_EDGES 1600000
#define D       64
#define CAP     64          // ELL row capacity; Poisson(16) => P(deg>64) ~ 1e-20

#define GEMM_BLOCKS (N_PAD / 128)                  // 782
#define FILL_BLOCKS ((N_EDGES / 8 + 255) / 256)    // 782

using namespace nvcuda;

// ---------------------------------------------------------------------------
// Scratch (allocation-free rule: __device__ globals). Zero-initialized at
// module load. g_deg is left zeroed by the gather kernel after each launch.
// Rows >= N_NODES of g_yh are written as zeros by the GEMM (zero-padded x),
// so the gather's dummy row N_NODES is always 0.
// ---------------------------------------------------------------------------
__device__ int    g_deg[N_NODES];
__device__ int    g_adj[(size_t)N_NODES * CAP];    // 25.6 MB, ELL layout
__device__ __half g_yh[(size_t)N_PAD * D];         // 12.8 MB, y = x @ W (fp16)

// ---------------------------------------------------------------------------
// Kernel 1 (fused): blocks [0, GEMM_BLOCKS): wmma GEMM y = x @ W
//   (x, W converted to fp16 in smem; fp32 accumulate; fp16 output).
// blocks [GEMM_BLOCKS, +FILL_BLOCKS): ELL fill (8 edges/thread).
// The halves touch disjoint data and overlap freely; the latency-bound fill
// hides under the tensor-core GEMM.
// ---------------------------------------------------------------------------
__global__ void gemm_fill_kernel(const float* __restrict__ x,
                                 const float* __restrict__ W,
                                 const int*   __restrict__ ei) {
    int t = threadIdx.x;   // 0..255

    if (blockIdx.x >= GEMM_BLOCKS) {
        // ---------------- ELL fill: 8 edges per thread ----------------
        int i = (blockIdx.x - GEMM_BLOCKS) * 256 + t;
        int e = i * 8;
        if (e >= N_EDGES) return;   // N_EDGES % 8 == 0

        int4 sa = *reinterpret_cast<const int4*>(&ei[e]);
        int4 sb = *reinterpret_cast<const int4*>(&ei[e + 4]);
        int4 ta = *reinterpret_cast<const int4*>(&ei[N_EDGES + e]);
        int4 tb = *reinterpret_cast<const int4*>(&ei[N_EDGES + e + 4]);

        int s[8]  = { sa.x, sa.y, sa.z, sa.w, sb.x, sb.y, sb.z, sb.w };
        int tt[8] = { ta.x, ta.y, ta.z, ta.w, tb.x, tb.y, tb.z, tb.w };

        int p[8];
#pragma unroll
        for (int u = 0; u < 8; u++) p[u] = atomicAdd(&g_deg[s[u]], 1);
#pragma unroll
        for (int u = 0; u < 8; u++)
            if (p[u] < CAP) g_adj[(long)s[u] * CAP + p[u]] = tt[u];
        return;
    }

    // ---------------- wmma GEMM: 128 rows per block, 16 per warp ----------
    __shared__ alignas(16) __half sW[D * D];        //  8 KB
    __shared__ alignas(16) __half sX[128 * D];      // 16 KB
    __shared__ alignas(16) float  stage[8 * 256];   //  8 KB (per-warp 16x16)

    int rows0 = blockIdx.x * 128;
    int w     = t >> 5;        // warp 0..7
    int lane  = t & 31;

    // Convert W -> fp16 smem (1024 float4, 4 per thread)
    {
        const float4* W4 = reinterpret_cast<const float4*>(W);
        uint2* dst = reinterpret_cast<uint2*>(sW);
#pragma unroll
        for (int i = 0; i < 4; i++) {
            int f = t + i * 256;
            float4 v = W4[f];
            __half2 h0 = __floats2half2_rn(v.x, v.y);
            __half2 h1 = __floats2half2_rn(v.z, v.w);
            dst[f] = make_uint2(*reinterpret_cast<unsigned int*>(&h0),
                                *reinterpret_cast<unsigned int*>(&h1));
        }
    }
    // Convert x tile -> fp16 smem (2048 float4, 8 per thread); pad rows = 0
    {
        const float4* X4 = reinterpret_cast<const float4*>(x);
        uint2* dst = reinterpret_cast<uint2*>(sX);
#pragma unroll
        for (int i = 0; i < 8; i++) {
            int f = t + i * 256;              // float4 index within tile
            int gn = rows0 + (f >> 4);        // global row
            float4 v = make_float4(0.f, 0.f, 0.f, 0.f);
            if (gn < N_NODES)
                v = X4[(size_t)gn * (D / 4) + (f & 15)];
            __half2 h0 = __floats2half2_rn(v.x, v.y);
            __half2 h1 = __floats2half2_rn(v.z, v.w);
            dst[f] = make_uint2(*reinterpret_cast<unsigned int*>(&h0),
                                *reinterpret_cast<unsigned int*>(&h1));
        }
    }
    __syncthreads();

    // A fragments for this warp's 16 rows (k = 0..3)
    wmma::fragment<wmma::matrix_a, 16, 16, 16, __half, wmma::row_major> af[4];
#pragma unroll
    for (int k = 0; k < 4; k++)
        wmma::load_matrix_sync(af[k], sX + (w * 16) * D + k * 16, D);

    float* st = stage + w * 256;

#pragma unroll
    for (int n = 0; n < 4; n++) {
        wmma::fragment<wmma::accumulator, 16, 16, 16, float> cf;
        wmma::fill_fragment(cf, 0.0f);
#pragma unroll
        for (int k = 0; k < 4; k++) {
            wmma::fragment<wmma::matrix_b, 16, 16, 16, __half, wmma::row_major> bf;
            wmma::load_matrix_sync(bf, sW + (k * 16) * D + n * 16, D);
            wmma::mma_sync(cf, af[k], bf, cf);
        }
        wmma::store_matrix_sync(st, cf, 16, wmma::mem_row_major);
        __syncwarp();

        // convert + store this 16x16 tile: lane -> (row = lane>>1, 8 cols)
        int r  = lane >> 1;
        int c0 = (lane & 1) * 8;
        int grow = rows0 + w * 16 + r;
        const float* sp = st + r * 16 + c0;
        __half2 h0 = __floats2half2_rn(sp[0], sp[1]);
        __half2 h1 = __floats2half2_rn(sp[2], sp[3]);
        __half2 h2 = __floats2half2_rn(sp[4], sp[5]);
        __half2 h3 = __floats2half2_rn(sp[6], sp[7]);
        uint4 pk = make_uint4(*reinterpret_cast<unsigned int*>(&h0),
                              *reinterpret_cast<unsigned int*>(&h1),
                              *reinterpret_cast<unsigned int*>(&h2),
                              *reinterpret_cast<unsigned int*>(&h3));
        reinterpret_cast<uint4*>(g_yh)[((size_t)grow * D + n * 16 + c0) / 8] = pk;
        __syncwarp();
    }
}

// ---------------------------------------------------------------------------
// Kernel 2: gather over y + normalize + bias -> out (final)
// EXACT R9 structure (measured 36.0 us). One warp per node.
// Lane = (slot, colgrp): slot=lane>>3, cg=lane&7.
// Degree-adaptive: neighbors 0..15 unconditional, 16..31 warp-uniform branch,
// 32..63 rare tail. Resets g_deg[node]=0 for the next launch.
// ---------------------------------------------------------------------------
__device__ __forceinline__ void acc_chunk(float acc[8], uint4 v) {
    float2 f0 = __half22float2(*reinterpret_cast<__half2*>(&v.x));
    float2 f1 = __half22float2(*reinterpret_cast<__half2*>(&v.y));
    float2 f2 = __half22float2(*reinterpret_cast<__half2*>(&v.z));
    float2 f3 = __half22float2(*reinterpret_cast<__half2*>(&v.w));
    acc[0] += f0.x; acc[1] += f0.y;
    acc[2] += f1.x; acc[3] += f1.y;
    acc[4] += f2.x; acc[5] += f2.y;
    acc[6] += f3.x; acc[7] += f3.y;
}

__global__ void gather_kernel(const float* __restrict__ b,
                              float*       __restrict__ out) {
    int node = (blockIdx.x * blockDim.x + threadIdx.x) >> 5;
    int lane = threadIdx.x & 31;
    if (node >= N_NODES) return;

    int slot = lane >> 3;
    int cg   = lane & 7;

    const int* arow = &g_adj[(long)node * CAP];
    // independent loads: deg, adj row (unpredicated — always in bounds)
    int deg_raw = g_deg[node];
    int a0 = arow[lane];

    // reset for the next launch (replaces the zeroing kernel)
    if (lane == 0) g_deg[node] = 0;

    int deg = deg_raw > CAP ? CAP : deg_raw;
    int d0  = deg < 32 ? deg : 32;

    const uint4* y4 = reinterpret_cast<const uint4*>(g_yh);

    float acc[8];
#pragma unroll
    for (int i = 0; i < 8; i++) acc[i] = 0.f;

    // ---- neighbors 0..15: unconditional, 4 independent loads per lane ----
    {
        int tn[4];
        uint4 v[4];
#pragma unroll
        for (int u = 0; u < 4; u++) {
            int j = u * 4 + slot;                    // 0..15
            int id = __shfl_sync(0xFFFFFFFFu, a0, j);
            tn[u] = (j < d0) ? id : N_NODES;         // dummy zero row
        }
#pragma unroll
        for (int u = 0; u < 4; u++) v[u] = y4[(size_t)tn[u] * 8 + cg];
#pragma unroll
        for (int u = 0; u < 4; u++) acc_chunk(acc, v[u]);
    }
    // ---- neighbors 16..31: warp-uniform branch (P ~ 0.43) ----
    if (d0 > 16) {
        int tn[4];
        uint4 v[4];
#pragma unroll
        for (int u = 0; u < 4; u++) {
            int j = 16 + u * 4 + slot;               // 16..31
            int id = __shfl_sync(0xFFFFFFFFu, a0, j);
            tn[u] = (j < d0) ? id : N_NODES;
        }
#pragma unroll
        for (int u = 0; u < 4; u++) v[u] = y4[(size_t)tn[u] * 8 + cg];
#pragma unroll
        for (int u = 0; u < 4; u++) acc_chunk(acc, v[u]);
    }
    // ---- neighbors 32..63: rare tail (P(deg>32) ~ 1e-4) ----
    if (deg > 32) {
        int a1 = arow[32 + lane];
        int tn[8];
        uint4 v[8];
#pragma unroll
        for (int u = 0; u < 8; u++) {
            int j = 32 + u * 4 + slot;               // 32..63
            int id = __shfl_sync(0xFFFFFFFFu, a1, j - 32);
            tn[u] = (j < deg) ? id : N_NODES;
        }
#pragma unroll
        for (int u = 0; u < 8; u++) v[u] = y4[(size_t)tn[u] * 8 + cg];
#pragma unroll
        for (int u = 0; u < 8; u++) acc_chunk(acc, v[u]);
    }

    // reduce across the 4 slots
#pragma unroll
    for (int i = 0; i < 8; i++) acc[i] += __shfl_xor_sync(0xFFFFFFFFu, acc[i], 8);
#pragma unroll
    for (int i = 0; i < 8; i++) acc[i] += __shfl_xor_sync(0xFFFFFFFFu, acc[i], 16);

    if (slot == 0) {
        float scale = 1.0f / ((float)deg_raw + 1e-6f);
        float4 b0 = reinterpret_cast<const float4*>(b)[cg * 2];
        float4 b1 = reinterpret_cast<const float4*>(b)[cg * 2 + 1];
        float4 o0 = make_float4(acc[0] * scale + b0.x, acc[1] * scale + b0.y,
                                acc[2] * scale + b0.z, acc[3] * scale + b0.w);
        float4 o1 = make_float4(acc[4] * scale + b1.x, acc[5] * scale + b1.y,
                                acc[6] * scale + b1.z, acc[7] * scale + b1.w);
        float4* dst = reinterpret_cast<float4*>(&out[(size_t)node * D + cg * 8]);
        dst[0] = o0;
        dst[1] = o1;
    }
}

// ---------------------------------------------------------------------------
// Launch
// ---------------------------------------------------------------------------
extern "C" void kernel_launch(void* const* d_in, const int* in_sizes, int n_in,
                              void* d_out, int out_size) {
    const float* x  = (const float*)d_in[0];   // [N, 64]
    const int*   ei = (const int*)  d_in[1];   // [2, E]
    const float* W  = (const float*)d_in[2];   // [64, 64]
    const float* b  = (const float*)d_in[3];   // [64]
    float* out = (float*)d_out;                // [N, 64]

    (void)in_sizes; (void)n_in; (void)out_size;

    gemm_fill_kernel<<<GEMM_BLOCKS + FILL_BLOCKS, 256>>>(x, W, ei);

    // one warp per node, 8 warps per block
    gather_kernel<<<(N_NODES + 7) / 8, 256>>>(b, out);
}